// round 1
// baseline (speedup 1.0000x reference)
#include <cuda_runtime.h>
#include <math.h>

#define U_CNT 50000
#define I_CNT 25000
#define DIM 64
#define N_CNT 75000
#define E2 2000000
#define BSZ 4096
#define ND (N_CNT*DIM)
#define EPSV 0.2f
#define INV_TEMP 5.0f
#define REG_LAMBDA 1e-4f
#define SSL_LAMBDA 0.2f
#define NSPLIT 8
#define RPB 128
#define TJ 128

// ---- device scratch (static allocation only; no runtime allocs) ----
__device__ __align__(256) float g_x[ND];
__device__ __align__(256) float g_y[ND];
__device__ __align__(256) float g_sum[ND];
__device__ __align__(256) float g_cl[ND];
__device__ __align__(16) float g_vucl[BSZ*DIM];
__device__ __align__(16) float g_vuemb[BSZ*DIM];
__device__ __align__(16) float g_vicl[BSZ*DIM];
__device__ __align__(16) float g_viemb[BSZ*DIM];
__device__ float g_part[BSZ*NSPLIT];
__device__ float g_acc[4];   // 0: bpr sum, 1: reg sum, 2: ssl_user sum, 3: ssl_item sum

__device__ __forceinline__ float wred(float v) {
#pragma unroll
    for (int o = 16; o; o >>= 1) v += __shfl_xor_sync(0xffffffffu, v, o);
    return v;
}

// ---- init: x = concat(user_table, item_table); zero y, sum, acc ----
__global__ void k_init(const float* __restrict__ ut, const float* __restrict__ itab) {
    int i = blockIdx.x * blockDim.x + threadIdx.x;
    if (i < ND) {
        g_x[i] = (i < U_CNT * DIM) ? ut[i] : itab[i - U_CNT * DIM];
        g_y[i] = 0.f;
        g_sum[i] = 0.f;
    }
    if (i < 4) g_acc[i] = 0.f;
}

// ---- SpMM scatter: out[src] += val * x[dst], 16 threads (one float4 each) per edge ----
__global__ void k_spmm(const float* __restrict__ xin, float* __restrict__ xout,
                       const int* __restrict__ src, const int* __restrict__ dst,
                       const float* __restrict__ val) {
    long long tid = (long long)blockIdx.x * blockDim.x + threadIdx.x;
    int e = (int)(tid >> 4);
    if (e >= E2) return;
    int q = (int)(tid & 15);
    int s = src[e], d = dst[e];
    float w = __ldg(val + e);
    float4 v = __ldg(((const float4*)(xin + (size_t)d * DIM)) + q);
    float4 r = make_float4(v.x * w, v.y * w, v.z * w, v.w * w);
    atomicAdd(((float4*)(xout + (size_t)s * DIM)) + q, r);  // red.global.v4.f32 (sm_90+)
}

// ---- perturb in place, accumulate into g_sum, optionally snapshot CL layer, zero next buf ----
__global__ void k_perturb(float* __restrict__ x, const float* __restrict__ noise,
                          float* __restrict__ zbuf, float* __restrict__ clbuf) {
    int gt = blockIdx.x * blockDim.x + threadIdx.x;
    int row = gt >> 5, lane = gt & 31;
    if (row >= N_CNT) return;
    size_t off = (size_t)row * DIM + lane * 2;
    float2 nz = *(const float2*)(noise + off);
    float ss = wred(nz.x * nz.x + nz.y * nz.y);
    float sc = EPSV / fmaxf(sqrtf(ss), 1e-12f);
    float2 v = *(float2*)(x + off);
    float sx = (v.x > 0.f) ? 1.f : ((v.x < 0.f) ? -1.f : 0.f);
    float sy = (v.y > 0.f) ? 1.f : ((v.y < 0.f) ? -1.f : 0.f);
    v.x += sx * nz.x * sc;
    v.y += sy * nz.y * sc;
    *(float2*)(x + off) = v;
    float2 sm = *(float2*)(g_sum + off);
    sm.x += v.x; sm.y += v.y;
    *(float2*)(g_sum + off) = sm;
    if (clbuf) *(float2*)(clbuf + off) = v;
    if (zbuf)  *(float2*)(zbuf + off) = make_float2(0.f, 0.f);
}

// ---- gather + l2-normalize SSL inputs (note: l2norm(sum/3) == l2norm(sum)) ----
__device__ __forceinline__ void norm_copy(const float* __restrict__ srcrow,
                                          float* __restrict__ dstrow, int lane) {
    float2 v = *(const float2*)(srcrow + lane * 2);
    float ss = wred(v.x * v.x + v.y * v.y);
    float inv = 1.f / fmaxf(sqrtf(ss), 1e-12f);
    *(float2*)(dstrow + lane * 2) = make_float2(v.x * inv, v.y * inv);
}

__global__ void k_prep(const int* __restrict__ user, const int* __restrict__ pos) {
    int gt = blockIdx.x * blockDim.x + threadIdx.x;
    int k = gt >> 5, lane = gt & 31;
    if (k >= BSZ) return;
    size_t ru = (size_t)user[k] * DIM;
    size_t ri = (size_t)(U_CNT + pos[k]) * DIM;
    norm_copy(g_cl + ru, g_vucl + (size_t)k * DIM, lane);
    norm_copy(g_sum + ru, g_vuemb + (size_t)k * DIM, lane);
    norm_copy(g_cl + ri, g_vicl + (size_t)k * DIM, lane);
    norm_copy(g_sum + ri, g_viemb + (size_t)k * DIM, lane);
}

// ---- BPR + reg partials: one warp per sample ----
__global__ void k_bpr(const float* __restrict__ ut, const float* __restrict__ itab,
                      const int* __restrict__ user, const int* __restrict__ pos,
                      const int* __restrict__ neg) {
    __shared__ float sh0[8], sh1[8];
    int gt = blockIdx.x * blockDim.x + threadIdx.x;
    int k = gt >> 5, lane = gt & 31, w = threadIdx.x >> 5;
    float sp = 0.f, rg = 0.f;
    if (k < BSZ) {
        int iu = user[k], ip = pos[k], ineg = neg[k];
        const float c = 1.f / 3.f;
        float2 ue = *(const float2*)(g_sum + (size_t)iu * DIM + lane * 2);
        float2 pe = *(const float2*)(g_sum + (size_t)(U_CNT + ip) * DIM + lane * 2);
        float2 ne = *(const float2*)(g_sum + (size_t)(U_CNT + ineg) * DIM + lane * 2);
        ue.x *= c; ue.y *= c; pe.x *= c; pe.y *= c; ne.x *= c; ne.y *= c;
        float ps = wred(ue.x * pe.x + ue.y * pe.y);
        float ns = wred(ue.x * ne.x + ue.y * ne.y);
        float2 a = *(const float2*)(ut + (size_t)iu * DIM + lane * 2);
        float2 b = *(const float2*)(itab + (size_t)ip * DIM + lane * 2);
        float2 d = *(const float2*)(itab + (size_t)ineg * DIM + lane * 2);
        float r = wred(a.x * a.x + a.y * a.y + b.x * b.x + b.y * b.y + d.x * d.x + d.y * d.y);
        if (lane == 0) {
            float z = ns - ps;
            sp = fmaxf(z, 0.f) + log1pf(expf(-fabsf(z)));
            rg = r;
        }
    }
    if (lane == 0) { sh0[w] = sp; sh1[w] = rg; }
    __syncthreads();
    if (threadIdx.x == 0) {
        float a = 0.f, b = 0.f;
#pragma unroll
        for (int i = 0; i < 8; i++) { a += sh0[i]; b += sh1[i]; }
        atomicAdd(&g_acc[0], a);
        atomicAdd(&g_acc[1], b);
    }
}

// ---- SSL partial: sum_j exp(5*dot(v1[i],v2[j]) - 5) over a j-chunk.
//      |dot| <= 1 (normalized rows) so max score is exactly 5 -> fixed-shift logsumexp. ----
__global__ void __launch_bounds__(RPB) k_ssl(const float* __restrict__ v1,
                                             const float* __restrict__ v2) {
    __shared__ float4 tile[TJ * 16];
    int i = blockIdx.x * RPB + threadIdx.x;
    const float4* v1f = (const float4*)v1;
    const float4* v2f = (const float4*)v2;
    float4 a[16];
#pragma unroll
    for (int q = 0; q < 16; q++) a[q] = v1f[(size_t)i * 16 + q];
    int j0 = blockIdx.y * (BSZ / NSPLIT);
    float s = 0.f;
    for (int jt = 0; jt < BSZ / NSPLIT; jt += TJ) {
        __syncthreads();
#pragma unroll
        for (int t = 0; t < 16; t++)
            tile[threadIdx.x + t * RPB] = v2f[(size_t)(j0 + jt) * 16 + threadIdx.x + t * RPB];
        __syncthreads();
        for (int jj = 0; jj < TJ; jj++) {
            const float4* tr = &tile[jj * 16];
            float d0 = 0.f, d1 = 0.f, d2 = 0.f, d3 = 0.f;
#pragma unroll
            for (int q = 0; q < 16; q += 4) {
                float4 t0 = tr[q], t1 = tr[q + 1], t2 = tr[q + 2], t3 = tr[q + 3];
                d0 += a[q].x * t0.x + a[q].y * t0.y + a[q].z * t0.z + a[q].w * t0.w;
                d1 += a[q + 1].x * t1.x + a[q + 1].y * t1.y + a[q + 1].z * t1.z + a[q + 1].w * t1.w;
                d2 += a[q + 2].x * t2.x + a[q + 2].y * t2.y + a[q + 2].z * t2.z + a[q + 2].w * t2.w;
                d3 += a[q + 3].x * t3.x + a[q + 3].y * t3.y + a[q + 3].z * t3.z + a[q + 3].w * t3.w;
            }
            float z = (d0 + d1 + d2 + d3) * INV_TEMP;
            s += __expf(z - 5.0f);
        }
    }
    g_part[(size_t)i * NSPLIT + blockIdx.y] = s;
}

// ---- SSL combine: ttl = 5 + log(sum partials); subtract pos score; reduce mean-sum ----
__global__ void k_sslfin(const float* __restrict__ v1, const float* __restrict__ v2, int accIdx) {
    __shared__ float sh[8];
    int i = blockIdx.x * blockDim.x + threadIdx.x;
    float val = 0.f;
    if (i < BSZ) {
        float s = 0.f;
#pragma unroll
        for (int c = 0; c < NSPLIT; c++) s += g_part[(size_t)i * NSPLIT + c];
        float ttl = 5.0f + logf(s);
        const float4* af = (const float4*)v1 + (size_t)i * 16;
        const float4* bf = (const float4*)v2 + (size_t)i * 16;
        float pd = 0.f;
#pragma unroll
        for (int q = 0; q < 16; q++) {
            float4 x = af[q], y = bf[q];
            pd += x.x * y.x + x.y * y.y + x.z * y.z + x.w * y.w;
        }
        val = ttl - pd * INV_TEMP;
    }
    val = wred(val);
    int lane = threadIdx.x & 31, w = threadIdx.x >> 5;
    if (lane == 0) sh[w] = val;
    __syncthreads();
    if (threadIdx.x == 0) {
        float a = 0.f;
#pragma unroll
        for (int q = 0; q < 8; q++) a += sh[q];
        atomicAdd(&g_acc[accIdx], a);
    }
}

__global__ void k_final(float* __restrict__ out) {
    if (threadIdx.x == 0) {
        out[0] = g_acc[0] / (float)BSZ;
        out[1] = REG_LAMBDA * 0.5f * g_acc[1] / (float)BSZ;
        out[2] = SSL_LAMBDA * (g_acc[2] / (float)BSZ + g_acc[3] / (float)BSZ);
    }
}

extern "C" void kernel_launch(void* const* d_in, const int* in_sizes, int n_in,
                              void* d_out, int out_size) {
    const float* ut   = (const float*)d_in[0];
    const float* itab = (const float*)d_in[1];
    const float* eval = (const float*)d_in[2];
    const float* noise= (const float*)d_in[3];
    const int*   esrc = (const int*)d_in[4];
    const int*   edst = (const int*)d_in[5];
    const int*   user = (const int*)d_in[6];
    const int*   pos  = (const int*)d_in[7];
    const int*   neg  = (const int*)d_in[8];
    float* out = (float*)d_out;

    float *px, *py, *pcl, *pucl, *puemb, *picl, *piemb;
    cudaGetSymbolAddress((void**)&px, g_x);
    cudaGetSymbolAddress((void**)&py, g_y);
    cudaGetSymbolAddress((void**)&pcl, g_cl);
    cudaGetSymbolAddress((void**)&pucl, g_vucl);
    cudaGetSymbolAddress((void**)&puemb, g_vuemb);
    cudaGetSymbolAddress((void**)&picl, g_vicl);
    cudaGetSymbolAddress((void**)&piemb, g_viemb);

    const int spmm_blocks = (int)(((long long)E2 * 16 + 255) / 256);
    const int pert_blocks = (N_CNT * 32 + 255) / 256;

    k_init<<<(ND + 255) / 256, 256>>>(ut, itab);

    // layer 0 (CL layer)
    k_spmm<<<spmm_blocks, 256>>>(px, py, esrc, edst, eval);
    k_perturb<<<pert_blocks, 256>>>(py, noise, px, pcl);
    // layer 1
    k_spmm<<<spmm_blocks, 256>>>(py, px, esrc, edst, eval);
    k_perturb<<<pert_blocks, 256>>>(px, noise + ND, py, nullptr);
    // layer 2
    k_spmm<<<spmm_blocks, 256>>>(px, py, esrc, edst, eval);
    k_perturb<<<pert_blocks, 256>>>(py, noise + 2 * (size_t)ND, nullptr, nullptr);

    k_prep<<<(BSZ * 32 + 255) / 256, 256>>>(user, pos);
    k_bpr<<<(BSZ * 32 + 255) / 256, 256>>>(ut, itab, user, pos, neg);

    dim3 sg(BSZ / RPB, NSPLIT);
    k_ssl<<<sg, RPB>>>(pucl, puemb);
    k_sslfin<<<BSZ / 256, 256>>>(pucl, puemb, 2);
    k_ssl<<<sg, RPB>>>(picl, piemb);
    k_sslfin<<<BSZ / 256, 256>>>(picl, piemb, 3);

    k_final<<<1, 32>>>(out);
}

// round 2
// speedup vs baseline: 1.5426x; 1.5426x over previous
#include <cuda_runtime.h>
#include <math.h>

#define U_CNT 50000
#define I_CNT 25000
#define DIM 64
#define N_CNT 75000
#define E2 2000000
#define BSZ 4096
#define ND (N_CNT*DIM)
#define EPSV 0.2f
#define REG_LAMBDA 1e-4f
#define SSL_LAMBDA 0.2f
#define SCAN_BLOCKS 74   // ceil(75001/1024)
#define SSL_NSPLIT 32
#define SSL_TJ 128

// ---- device scratch (static allocation only) ----
__device__ __align__(256) float g_x[ND];
__device__ __align__(256) float g_y[ND];
__device__ __align__(256) float g_sum[ND];
__device__ __align__(256) float g_cl[ND];
__device__ __align__(16) int2  g_epack[E2];
__device__ int g_off[N_CNT + 8];
__device__ int g_scan[N_CNT + 8];
__device__ int g_wp[N_CNT + 8];
__device__ int g_bsum[SCAN_BLOCKS];
__device__ int g_boff[SCAN_BLOCKS];
__device__ __align__(16) float g_vucl[BSZ*DIM];
__device__ __align__(16) float g_vuemb[BSZ*DIM];
__device__ __align__(16) float g_vicl[BSZ*DIM];
__device__ __align__(16) float g_viemb[BSZ*DIM];
__device__ float g_part[2 * BSZ * SSL_NSPLIT];
__device__ float g_acc[4];   // 0: bpr, 1: reg, 2: ssl_user, 3: ssl_item

__device__ __forceinline__ float wred(float v) {
#pragma unroll
    for (int o = 16; o; o >>= 1) v += __shfl_xor_sync(0xffffffffu, v, o);
    return v;
}
__device__ __forceinline__ int wscan_i(int v, int lane) {
#pragma unroll
    for (int o = 1; o < 32; o <<= 1) {
        int t = __shfl_up_sync(0xffffffffu, v, o);
        if (lane >= o) v += t;
    }
    return v;
}

// ---- init: x = concat(tables); zero g_off histogram + acc ----
__global__ void k_init(const float* __restrict__ ut, const float* __restrict__ itab) {
    int i = blockIdx.x * blockDim.x + threadIdx.x;
    if (i < ND)
        g_x[i] = (i < U_CNT * DIM) ? ut[i] : itab[i - U_CNT * DIM];
    if (i <= N_CNT) g_off[i] = 0;
    if (i < 4) g_acc[i] = 0.f;
}

// ---- CSR build: histogram (shifted by 1 for exclusive offsets) ----
__global__ void k_hist(const int* __restrict__ src) {
    int e = blockIdx.x * blockDim.x + threadIdx.x;
    if (e < E2) atomicAdd(&g_off[src[e] + 1], 1);
}

// ---- block-level inclusive scan of g_off[0..N_CNT] ----
__global__ void k_scan1() {
    __shared__ int ws[32];
    int i = blockIdx.x * 1024 + threadIdx.x;
    int v = (i <= N_CNT) ? g_off[i] : 0;
    int lane = threadIdx.x & 31, wid = threadIdx.x >> 5;
    int s = wscan_i(v, lane);
    if (lane == 31) ws[wid] = s;
    __syncthreads();
    if (wid == 0) { int t = ws[lane]; t = wscan_i(t, lane); ws[lane] = t; }
    __syncthreads();
    if (wid) s += ws[wid - 1];
    if (i <= N_CNT) g_scan[i] = s;
    if (threadIdx.x == 1023) g_bsum[blockIdx.x] = s;
}

// ---- scan of SCAN_BLOCKS block totals (single warp, 3 segments) ----
__global__ void k_scan2() {
    int lane = threadIdx.x;
    int v0 = (lane < SCAN_BLOCKS) ? g_bsum[lane] : 0;
    int v1 = (32 + lane < SCAN_BLOCKS) ? g_bsum[32 + lane] : 0;
    int v2 = (64 + lane < SCAN_BLOCKS) ? g_bsum[64 + lane] : 0;
    int s0 = wscan_i(v0, lane);
    int t0 = __shfl_sync(0xffffffffu, s0, 31);
    int s1 = wscan_i(v1, lane) + t0;
    int t1 = __shfl_sync(0xffffffffu, s1, 31);
    int s2 = wscan_i(v2, lane) + t1;
    if (lane < SCAN_BLOCKS) g_boff[lane] = s0 - v0;
    if (32 + lane < SCAN_BLOCKS) g_boff[32 + lane] = s1 - v1;
    if (64 + lane < SCAN_BLOCKS) g_boff[64 + lane] = s2 - v2;
}

// ---- finalize offsets + init write pointers ----
__global__ void k_scan3() {
    int i = blockIdx.x * blockDim.x + threadIdx.x;
    if (i <= N_CNT) {
        int v = g_scan[i] + g_boff[i >> 10];
        g_off[i] = v;
        if (i < N_CNT) g_wp[i] = v;
    }
}

// ---- scatter edges into CSR order as packed (dst, val) ----
__global__ void k_scatter(const int* __restrict__ src, const int* __restrict__ dst,
                          const float* __restrict__ val) {
    int e = blockIdx.x * blockDim.x + threadIdx.x;
    if (e >= E2) return;
    int r = src[e];
    int p = atomicAdd(&g_wp[r], 1);
    g_epack[p] = make_int2(dst[e], __float_as_int(val[e]));
}

// ---- fused layer: CSR gather + perturb + mean-accum + optional CL snapshot ----
__global__ void k_layer(const float* __restrict__ xin, float* __restrict__ xout,
                        const float* __restrict__ noise, float* __restrict__ cl, int first) {
    int gt = blockIdx.x * blockDim.x + threadIdx.x;
    int row = gt >> 5, lane = gt & 31;
    if (row >= N_CNT) return;
    int k = g_off[row], end = g_off[row + 1];
    float ax = 0.f, ay = 0.f;
    for (; k + 2 <= end; k += 2) {
        int2 e0 = __ldg(&g_epack[k]);
        int2 e1 = __ldg(&g_epack[k + 1]);
        float2 v0 = *(const float2*)(xin + (size_t)e0.x * DIM + lane * 2);
        float2 v1 = *(const float2*)(xin + (size_t)e1.x * DIM + lane * 2);
        float w0 = __int_as_float(e0.y), w1 = __int_as_float(e1.y);
        ax = fmaf(w0, v0.x, fmaf(w1, v1.x, ax));
        ay = fmaf(w0, v0.y, fmaf(w1, v1.y, ay));
    }
    if (k < end) {
        int2 e0 = __ldg(&g_epack[k]);
        float2 v0 = *(const float2*)(xin + (size_t)e0.x * DIM + lane * 2);
        float w0 = __int_as_float(e0.y);
        ax = fmaf(w0, v0.x, ax);
        ay = fmaf(w0, v0.y, ay);
    }
    size_t off = (size_t)row * DIM + lane * 2;
    float2 nz = *(const float2*)(noise + off);
    float ss = wred(nz.x * nz.x + nz.y * nz.y);
    float sc = EPSV / fmaxf(sqrtf(ss), 1e-12f);
    float sx = (ax > 0.f) ? 1.f : ((ax < 0.f) ? -1.f : 0.f);
    float sy = (ay > 0.f) ? 1.f : ((ay < 0.f) ? -1.f : 0.f);
    ax += sx * nz.x * sc;
    ay += sy * nz.y * sc;
    *(float2*)(xout + off) = make_float2(ax, ay);
    float2 sm;
    if (first) sm = make_float2(ax, ay);
    else { sm = *(float2*)(g_sum + off); sm.x += ax; sm.y += ay; }
    *(float2*)(g_sum + off) = sm;
    if (cl) *(float2*)(cl + off) = make_float2(ax, ay);
}

// ---- gather + l2-normalize SSL inputs (l2norm(sum/3) == l2norm(sum)) ----
__device__ __forceinline__ void norm_copy(const float* __restrict__ srcrow,
                                          float* __restrict__ dstrow, int lane) {
    float2 v = *(const float2*)(srcrow + lane * 2);
    float ss = wred(v.x * v.x + v.y * v.y);
    float inv = 1.f / fmaxf(sqrtf(ss), 1e-12f);
    *(float2*)(dstrow + lane * 2) = make_float2(v.x * inv, v.y * inv);
}

__global__ void k_prep(const int* __restrict__ user, const int* __restrict__ pos) {
    int gt = blockIdx.x * blockDim.x + threadIdx.x;
    int k = gt >> 5, lane = gt & 31;
    if (k >= BSZ) return;
    size_t ru = (size_t)user[k] * DIM;
    size_t ri = (size_t)(U_CNT + pos[k]) * DIM;
    norm_copy(g_cl + ru, g_vucl + (size_t)k * DIM, lane);
    norm_copy(g_sum + ru, g_vuemb + (size_t)k * DIM, lane);
    norm_copy(g_cl + ri, g_vicl + (size_t)k * DIM, lane);
    norm_copy(g_sum + ri, g_viemb + (size_t)k * DIM, lane);
}

// ---- BPR + reg ----
__global__ void k_bpr(const float* __restrict__ ut, const float* __restrict__ itab,
                      const int* __restrict__ user, const int* __restrict__ pos,
                      const int* __restrict__ neg) {
    __shared__ float sh0[8], sh1[8];
    int gt = blockIdx.x * blockDim.x + threadIdx.x;
    int k = gt >> 5, lane = gt & 31, w = threadIdx.x >> 5;
    float sp = 0.f, rg = 0.f;
    if (k < BSZ) {
        int iu = user[k], ip = pos[k], ineg = neg[k];
        const float c = 1.f / 3.f;
        float2 ue = *(const float2*)(g_sum + (size_t)iu * DIM + lane * 2);
        float2 pe = *(const float2*)(g_sum + (size_t)(U_CNT + ip) * DIM + lane * 2);
        float2 ne = *(const float2*)(g_sum + (size_t)(U_CNT + ineg) * DIM + lane * 2);
        ue.x *= c; ue.y *= c; pe.x *= c; pe.y *= c; ne.x *= c; ne.y *= c;
        float ps = wred(ue.x * pe.x + ue.y * pe.y);
        float ns = wred(ue.x * ne.x + ue.y * ne.y);
        float2 a = *(const float2*)(ut + (size_t)iu * DIM + lane * 2);
        float2 b = *(const float2*)(itab + (size_t)ip * DIM + lane * 2);
        float2 d = *(const float2*)(itab + (size_t)ineg * DIM + lane * 2);
        float r = wred(a.x * a.x + a.y * a.y + b.x * b.x + b.y * b.y + d.x * d.x + d.y * d.y);
        if (lane == 0) {
            float z = ns - ps;
            sp = fmaxf(z, 0.f) + log1pf(expf(-fabsf(z)));
            rg = r;
        }
    }
    if (lane == 0) { sh0[w] = sp; sh1[w] = rg; }
    __syncthreads();
    if (threadIdx.x == 0) {
        float a = 0.f, b = 0.f;
#pragma unroll
        for (int i = 0; i < 8; i++) { a += sh0[i]; b += sh1[i]; }
        atomicAdd(&g_acc[0], a);
        atomicAdd(&g_acc[1], b);
    }
}

// ---- SSL partials: both matrices via blockIdx.z, 2 rows/thread register blocking.
//      |dot| <= 1 (normalized) -> fixed-shift logsumexp with max = 1/TEMP = 5. ----
__global__ void __launch_bounds__(128, 2) k_ssl2(
        const float* __restrict__ v1u, const float* __restrict__ v2u,
        const float* __restrict__ v1i, const float* __restrict__ v2i) {
    __shared__ float4 tile[SSL_TJ * 16];
    const float* v1 = blockIdx.z ? v1i : v1u;
    const float* v2 = blockIdx.z ? v2i : v2u;
    int i0 = blockIdx.x * 256 + threadIdx.x;   // this thread: rows i0, i0+128
    const float4* v1f = (const float4*)v1;
    const float4* v2f = (const float4*)v2;
    float4 a0[16], a1[16];
#pragma unroll
    for (int q = 0; q < 16; q++) {
        a0[q] = v1f[(size_t)i0 * 16 + q];
        a1[q] = v1f[(size_t)(i0 + 128) * 16 + q];
    }
    int j0 = blockIdx.y * SSL_TJ;
#pragma unroll
    for (int t = 0; t < 16; t++)
        tile[threadIdx.x + t * 128] = v2f[(size_t)j0 * 16 + threadIdx.x + t * 128];
    __syncthreads();
    float s0 = 0.f, s1 = 0.f;
    for (int jj = 0; jj < SSL_TJ; jj++) {
        const float4* tr = &tile[jj * 16];
        float d00 = 0.f, d01 = 0.f, d02 = 0.f, d03 = 0.f;
        float d10 = 0.f, d11 = 0.f, d12 = 0.f, d13 = 0.f;
#pragma unroll
        for (int q = 0; q < 16; q += 4) {
            float4 t0 = tr[q], t1 = tr[q + 1], t2 = tr[q + 2], t3 = tr[q + 3];
            d00 += a0[q].x * t0.x + a0[q].y * t0.y + a0[q].z * t0.z + a0[q].w * t0.w;
            d01 += a0[q+1].x * t1.x + a0[q+1].y * t1.y + a0[q+1].z * t1.z + a0[q+1].w * t1.w;
            d02 += a0[q+2].x * t2.x + a0[q+2].y * t2.y + a0[q+2].z * t2.z + a0[q+2].w * t2.w;
            d03 += a0[q+3].x * t3.x + a0[q+3].y * t3.y + a0[q+3].z * t3.z + a0[q+3].w * t3.w;
            d10 += a1[q].x * t0.x + a1[q].y * t0.y + a1[q].z * t0.z + a1[q].w * t0.w;
            d11 += a1[q+1].x * t1.x + a1[q+1].y * t1.y + a1[q+1].z * t1.z + a1[q+1].w * t1.w;
            d12 += a1[q+2].x * t2.x + a1[q+2].y * t2.y + a1[q+2].z * t2.z + a1[q+2].w * t2.w;
            d13 += a1[q+3].x * t3.x + a1[q+3].y * t3.y + a1[q+3].z * t3.z + a1[q+3].w * t3.w;
        }
        s0 += __expf(fmaf(d00 + d01 + d02 + d03, 5.0f, -5.0f));
        s1 += __expf(fmaf(d10 + d11 + d12 + d13, 5.0f, -5.0f));
    }
    size_t base = (size_t)blockIdx.z * BSZ;
    g_part[(base + i0) * SSL_NSPLIT + blockIdx.y] = s0;
    g_part[(base + i0 + 128) * SSL_NSPLIT + blockIdx.y] = s1;
}

// ---- SSL combine: ttl = 5 + log(sum partials); subtract pos score ----
__global__ void k_sslfin(const float* __restrict__ v1u, const float* __restrict__ v2u,
                         const float* __restrict__ v1i, const float* __restrict__ v2i) {
    __shared__ float sh[8];
    const float* v1 = blockIdx.y ? v1i : v1u;
    const float* v2 = blockIdx.y ? v2i : v2u;
    int i = blockIdx.x * blockDim.x + threadIdx.x;
    float s = 0.f;
    size_t base = ((size_t)blockIdx.y * BSZ + i) * SSL_NSPLIT;
#pragma unroll
    for (int c = 0; c < SSL_NSPLIT; c++) s += g_part[base + c];
    float ttl = 5.0f + logf(s);
    const float4* af = (const float4*)v1 + (size_t)i * 16;
    const float4* bf = (const float4*)v2 + (size_t)i * 16;
    float pd = 0.f;
#pragma unroll
    for (int q = 0; q < 16; q++) {
        float4 x = af[q], y = bf[q];
        pd += x.x * y.x + x.y * y.y + x.z * y.z + x.w * y.w;
    }
    float val = ttl - pd * 5.0f;
    val = wred(val);
    int lane = threadIdx.x & 31, w = threadIdx.x >> 5;
    if (lane == 0) sh[w] = val;
    __syncthreads();
    if (threadIdx.x == 0) {
        float a = 0.f;
#pragma unroll
        for (int q = 0; q < 8; q++) a += sh[q];
        atomicAdd(&g_acc[2 + blockIdx.y], a);
    }
}

__global__ void k_final(float* __restrict__ out) {
    if (threadIdx.x == 0) {
        out[0] = g_acc[0] / (float)BSZ;
        out[1] = REG_LAMBDA * 0.5f * g_acc[1] / (float)BSZ;
        out[2] = SSL_LAMBDA * (g_acc[2] / (float)BSZ + g_acc[3] / (float)BSZ);
    }
}

extern "C" void kernel_launch(void* const* d_in, const int* in_sizes, int n_in,
                              void* d_out, int out_size) {
    const float* ut   = (const float*)d_in[0];
    const float* itab = (const float*)d_in[1];
    const float* eval = (const float*)d_in[2];
    const float* noise= (const float*)d_in[3];
    const int*   esrc = (const int*)d_in[4];
    const int*   edst = (const int*)d_in[5];
    const int*   user = (const int*)d_in[6];
    const int*   pos  = (const int*)d_in[7];
    const int*   neg  = (const int*)d_in[8];
    float* out = (float*)d_out;

    float *px, *py, *pcl, *pucl, *puemb, *picl, *piemb;
    cudaGetSymbolAddress((void**)&px, g_x);
    cudaGetSymbolAddress((void**)&py, g_y);
    cudaGetSymbolAddress((void**)&pcl, g_cl);
    cudaGetSymbolAddress((void**)&pucl, g_vucl);
    cudaGetSymbolAddress((void**)&puemb, g_vuemb);
    cudaGetSymbolAddress((void**)&picl, g_vicl);
    cudaGetSymbolAddress((void**)&piemb, g_viemb);

    const int eb = (E2 + 255) / 256;
    const int lb = (N_CNT * 32 + 255) / 256;

    k_init<<<(ND + 255) / 256, 256>>>(ut, itab);
    k_hist<<<eb, 256>>>(esrc);
    k_scan1<<<SCAN_BLOCKS, 1024>>>();
    k_scan2<<<1, 32>>>();
    k_scan3<<<(N_CNT + 256) / 256, 256>>>();
    k_scatter<<<eb, 256>>>(esrc, edst, eval);

    k_layer<<<lb, 256>>>(px, py, noise, pcl, 1);
    k_layer<<<lb, 256>>>(py, px, noise + (size_t)ND, nullptr, 0);
    k_layer<<<lb, 256>>>(px, py, noise + 2 * (size_t)ND, nullptr, 0);

    k_prep<<<(BSZ * 32 + 255) / 256, 256>>>(user, pos);
    k_bpr<<<(BSZ * 32 + 255) / 256, 256>>>(ut, itab, user, pos, neg);

    dim3 sg(BSZ / 256, SSL_NSPLIT, 2);
    k_ssl2<<<sg, 128>>>(pucl, puemb, picl, piemb);
    dim3 fg(BSZ / 256, 2);
    k_sslfin<<<fg, 256>>>(pucl, puemb, picl, piemb);

    k_final<<<1, 32>>>(out);
}

// round 3
// speedup vs baseline: 1.7688x; 1.1467x over previous
#include <cuda_runtime.h>
#include <cuda_fp16.h>
#include <math.h>

#define U_CNT 50000
#define I_CNT 25000
#define DIM 64
#define N_CNT 75000
#define E2 2000000
#define BSZ 4096
#define ND (N_CNT*DIM)
#define EPSV 0.2f
#define REG_LAMBDA 1e-4f
#define SSL_LAMBDA 0.2f
#define SCAN_BLOCKS 74   // ceil(75001/1024)
#define SSL_NSPLIT 32
#define SSL_TJ 128

// ---- device scratch (static allocation only) ----
__device__ __align__(256) __half2 g_xh[N_CNT * 32];   // fp16 ping
__device__ __align__(256) __half2 g_yh[N_CNT * 32];   // fp16 pong
__device__ __align__(256) float g_sum[ND];            // fp32 accumulation
__device__ __align__(256) float g_cl[ND];             // fp32 CL snapshot
__device__ __align__(16) int2  g_epack[E2];
__device__ int g_off[N_CNT + 8];
__device__ int g_scan[N_CNT + 8];
__device__ int g_wp[N_CNT + 8];
__device__ int g_bsum[SCAN_BLOCKS];
__device__ int g_boff[SCAN_BLOCKS];
__device__ __align__(16) float g_vucl[BSZ*DIM];
__device__ __align__(16) float g_vuemb[BSZ*DIM];
__device__ __align__(16) float g_vicl[BSZ*DIM];
__device__ __align__(16) float g_viemb[BSZ*DIM];
__device__ float g_part[2 * BSZ * SSL_NSPLIT];
__device__ float g_acc[4];   // 0: bpr, 1: reg, 2: ssl_user, 3: ssl_item

__device__ __forceinline__ float wred(float v) {
#pragma unroll
    for (int o = 16; o; o >>= 1) v += __shfl_xor_sync(0xffffffffu, v, o);
    return v;
}
__device__ __forceinline__ int wscan_i(int v, int lane) {
#pragma unroll
    for (int o = 1; o < 32; o <<= 1) {
        int t = __shfl_up_sync(0xffffffffu, v, o);
        if (lane >= o) v += t;
    }
    return v;
}

// ---- init: xh = fp16(concat(tables)); zero histogram + acc ----
__global__ void k_init(const float* __restrict__ ut, const float* __restrict__ itab) {
    int i = blockIdx.x * blockDim.x + threadIdx.x;   // half2 index
    if (i < N_CNT * 32) {
        int fi = i * 2;
        float a = (fi < U_CNT * DIM) ? ut[fi] : itab[fi - U_CNT * DIM];
        float b = (fi + 1 < U_CNT * DIM) ? ut[fi + 1] : itab[fi + 1 - U_CNT * DIM];
        g_xh[i] = __floats2half2_rn(a, b);
    }
    if (i <= N_CNT) g_off[i] = 0;
    if (i < 4) g_acc[i] = 0.f;
}

// ---- CSR build: histogram (shifted by 1 for exclusive offsets) ----
__global__ void k_hist(const int* __restrict__ src) {
    int e = blockIdx.x * blockDim.x + threadIdx.x;
    if (e < E2) atomicAdd(&g_off[src[e] + 1], 1);
}

// ---- block-level inclusive scan of g_off[0..N_CNT] ----
__global__ void k_scan1() {
    __shared__ int ws[32];
    int i = blockIdx.x * 1024 + threadIdx.x;
    int v = (i <= N_CNT) ? g_off[i] : 0;
    int lane = threadIdx.x & 31, wid = threadIdx.x >> 5;
    int s = wscan_i(v, lane);
    if (lane == 31) ws[wid] = s;
    __syncthreads();
    if (wid == 0) { int t = ws[lane]; t = wscan_i(t, lane); ws[lane] = t; }
    __syncthreads();
    if (wid) s += ws[wid - 1];
    if (i <= N_CNT) g_scan[i] = s;
    if (threadIdx.x == 1023) g_bsum[blockIdx.x] = s;
}

// ---- scan of SCAN_BLOCKS block totals (single warp, 3 segments) ----
__global__ void k_scan2() {
    int lane = threadIdx.x;
    int v0 = (lane < SCAN_BLOCKS) ? g_bsum[lane] : 0;
    int v1 = (32 + lane < SCAN_BLOCKS) ? g_bsum[32 + lane] : 0;
    int v2 = (64 + lane < SCAN_BLOCKS) ? g_bsum[64 + lane] : 0;
    int s0 = wscan_i(v0, lane);
    int t0 = __shfl_sync(0xffffffffu, s0, 31);
    int s1 = wscan_i(v1, lane) + t0;
    int t1 = __shfl_sync(0xffffffffu, s1, 31);
    int s2 = wscan_i(v2, lane) + t1;
    if (lane < SCAN_BLOCKS) g_boff[lane] = s0 - v0;
    if (32 + lane < SCAN_BLOCKS) g_boff[32 + lane] = s1 - v1;
    if (64 + lane < SCAN_BLOCKS) g_boff[64 + lane] = s2 - v2;
}

// ---- finalize offsets + init write pointers ----
__global__ void k_scan3() {
    int i = blockIdx.x * blockDim.x + threadIdx.x;
    if (i <= N_CNT) {
        int v = g_scan[i] + g_boff[i >> 10];
        g_off[i] = v;
        if (i < N_CNT) g_wp[i] = v;
    }
}

// ---- scatter edges into CSR order as packed (dst, val) ----
__global__ void k_scatter(const int* __restrict__ src, const int* __restrict__ dst,
                          const float* __restrict__ val) {
    int e = blockIdx.x * blockDim.x + threadIdx.x;
    if (e >= E2) return;
    int r = src[e];
    int p = atomicAdd(&g_wp[r], 1);
    g_epack[p] = make_int2(dst[e], __float_as_int(val[e]));
}

// ---- fused layer: fp16 CSR gather (fp32 accum) + perturb + mean-accum + CL snapshot.
//      All consumed values (sum/cl) are fp32 pre-rounding; fp16 only feeds next gather. ----
__global__ void k_layer(const __half2* __restrict__ xin, __half2* __restrict__ xout,
                        const float* __restrict__ noise, float* __restrict__ cl, int first) {
    int gt = blockIdx.x * blockDim.x + threadIdx.x;
    int row = gt >> 5, lane = gt & 31;
    if (row >= N_CNT) return;
    int k = g_off[row], end = g_off[row + 1];
    float ax = 0.f, ay = 0.f;
    int n4 = k + ((end - k) & ~3);
    for (; k < n4; k += 4) {
        int2 e0 = __ldg(&g_epack[k]);
        int2 e1 = __ldg(&g_epack[k + 1]);
        int2 e2 = __ldg(&g_epack[k + 2]);
        int2 e3 = __ldg(&g_epack[k + 3]);
        float2 v0 = __half22float2(__ldg(xin + (size_t)e0.x * 32 + lane));
        float2 v1 = __half22float2(__ldg(xin + (size_t)e1.x * 32 + lane));
        float2 v2 = __half22float2(__ldg(xin + (size_t)e2.x * 32 + lane));
        float2 v3 = __half22float2(__ldg(xin + (size_t)e3.x * 32 + lane));
        float w0 = __int_as_float(e0.y), w1 = __int_as_float(e1.y);
        float w2 = __int_as_float(e2.y), w3 = __int_as_float(e3.y);
        ax = fmaf(w0, v0.x, fmaf(w1, v1.x, fmaf(w2, v2.x, fmaf(w3, v3.x, ax))));
        ay = fmaf(w0, v0.y, fmaf(w1, v1.y, fmaf(w2, v2.y, fmaf(w3, v3.y, ay))));
    }
    for (; k < end; k++) {
        int2 e0 = __ldg(&g_epack[k]);
        float2 v0 = __half22float2(__ldg(xin + (size_t)e0.x * 32 + lane));
        float w0 = __int_as_float(e0.y);
        ax = fmaf(w0, v0.x, ax);
        ay = fmaf(w0, v0.y, ay);
    }
    size_t off = (size_t)row * DIM + lane * 2;
    float2 nz = *(const float2*)(noise + off);
    float ss = wred(nz.x * nz.x + nz.y * nz.y);
    float sc = EPSV / fmaxf(sqrtf(ss), 1e-12f);
    float sx = (ax > 0.f) ? 1.f : ((ax < 0.f) ? -1.f : 0.f);
    float sy = (ay > 0.f) ? 1.f : ((ay < 0.f) ? -1.f : 0.f);
    ax += sx * nz.x * sc;
    ay += sy * nz.y * sc;
    xout[(size_t)row * 32 + lane] = __floats2half2_rn(ax, ay);
    float2 sm;
    if (first) sm = make_float2(ax, ay);
    else { sm = *(float2*)(g_sum + off); sm.x += ax; sm.y += ay; }
    *(float2*)(g_sum + off) = sm;
    if (cl) *(float2*)(cl + off) = make_float2(ax, ay);
}

// ---- gather + l2-normalize SSL inputs (l2norm(sum/3) == l2norm(sum)) ----
__device__ __forceinline__ void norm_copy(const float* __restrict__ srcrow,
                                          float* __restrict__ dstrow, int lane) {
    float2 v = *(const float2*)(srcrow + lane * 2);
    float ss = wred(v.x * v.x + v.y * v.y);
    float inv = 1.f / fmaxf(sqrtf(ss), 1e-12f);
    *(float2*)(dstrow + lane * 2) = make_float2(v.x * inv, v.y * inv);
}

__global__ void k_prep(const int* __restrict__ user, const int* __restrict__ pos) {
    int gt = blockIdx.x * blockDim.x + threadIdx.x;
    int k = gt >> 5, lane = gt & 31;
    if (k >= BSZ) return;
    size_t ru = (size_t)user[k] * DIM;
    size_t ri = (size_t)(U_CNT + pos[k]) * DIM;
    norm_copy(g_cl + ru, g_vucl + (size_t)k * DIM, lane);
    norm_copy(g_sum + ru, g_vuemb + (size_t)k * DIM, lane);
    norm_copy(g_cl + ri, g_vicl + (size_t)k * DIM, lane);
    norm_copy(g_sum + ri, g_viemb + (size_t)k * DIM, lane);
}

// ---- BPR + reg ----
__global__ void k_bpr(const float* __restrict__ ut, const float* __restrict__ itab,
                      const int* __restrict__ user, const int* __restrict__ pos,
                      const int* __restrict__ neg) {
    __shared__ float sh0[8], sh1[8];
    int gt = blockIdx.x * blockDim.x + threadIdx.x;
    int k = gt >> 5, lane = gt & 31, w = threadIdx.x >> 5;
    float sp = 0.f, rg = 0.f;
    if (k < BSZ) {
        int iu = user[k], ip = pos[k], ineg = neg[k];
        const float c = 1.f / 3.f;
        float2 ue = *(const float2*)(g_sum + (size_t)iu * DIM + lane * 2);
        float2 pe = *(const float2*)(g_sum + (size_t)(U_CNT + ip) * DIM + lane * 2);
        float2 ne = *(const float2*)(g_sum + (size_t)(U_CNT + ineg) * DIM + lane * 2);
        ue.x *= c; ue.y *= c; pe.x *= c; pe.y *= c; ne.x *= c; ne.y *= c;
        float ps = wred(ue.x * pe.x + ue.y * pe.y);
        float ns = wred(ue.x * ne.x + ue.y * ne.y);
        float2 a = *(const float2*)(ut + (size_t)iu * DIM + lane * 2);
        float2 b = *(const float2*)(itab + (size_t)ip * DIM + lane * 2);
        float2 d = *(const float2*)(itab + (size_t)ineg * DIM + lane * 2);
        float r = wred(a.x * a.x + a.y * a.y + b.x * b.x + b.y * b.y + d.x * d.x + d.y * d.y);
        if (lane == 0) {
            float z = ns - ps;
            sp = fmaxf(z, 0.f) + log1pf(expf(-fabsf(z)));
            rg = r;
        }
    }
    if (lane == 0) { sh0[w] = sp; sh1[w] = rg; }
    __syncthreads();
    if (threadIdx.x == 0) {
        float a = 0.f, b = 0.f;
#pragma unroll
        for (int i = 0; i < 8; i++) { a += sh0[i]; b += sh1[i]; }
        atomicAdd(&g_acc[0], a);
        atomicAdd(&g_acc[1], b);
    }
}

// ---- SSL partials: both matrices via blockIdx.z, 2 rows/thread register blocking.
//      |dot| <= 1 (normalized) -> fixed-shift logsumexp with max = 1/TEMP = 5. ----
__global__ void __launch_bounds__(128, 2) k_ssl2(
        const float* __restrict__ v1u, const float* __restrict__ v2u,
        const float* __restrict__ v1i, const float* __restrict__ v2i) {
    __shared__ float4 tile[SSL_TJ * 16];
    const float* v1 = blockIdx.z ? v1i : v1u;
    const float* v2 = blockIdx.z ? v2i : v2u;
    int i0 = blockIdx.x * 256 + threadIdx.x;   // this thread: rows i0, i0+128
    const float4* v1f = (const float4*)v1;
    const float4* v2f = (const float4*)v2;
    float4 a0[16], a1[16];
#pragma unroll
    for (int q = 0; q < 16; q++) {
        a0[q] = v1f[(size_t)i0 * 16 + q];
        a1[q] = v1f[(size_t)(i0 + 128) * 16 + q];
    }
    int j0 = blockIdx.y * SSL_TJ;
#pragma unroll
    for (int t = 0; t < 16; t++)
        tile[threadIdx.x + t * 128] = v2f[(size_t)j0 * 16 + threadIdx.x + t * 128];
    __syncthreads();
    float s0 = 0.f, s1 = 0.f;
    for (int jj = 0; jj < SSL_TJ; jj++) {
        const float4* tr = &tile[jj * 16];
        float d00 = 0.f, d01 = 0.f, d02 = 0.f, d03 = 0.f;
        float d10 = 0.f, d11 = 0.f, d12 = 0.f, d13 = 0.f;
#pragma unroll
        for (int q = 0; q < 16; q += 4) {
            float4 t0 = tr[q], t1 = tr[q + 1], t2 = tr[q + 2], t3 = tr[q + 3];
            d00 += a0[q].x * t0.x + a0[q].y * t0.y + a0[q].z * t0.z + a0[q].w * t0.w;
            d01 += a0[q+1].x * t1.x + a0[q+1].y * t1.y + a0[q+1].z * t1.z + a0[q+1].w * t1.w;
            d02 += a0[q+2].x * t2.x + a0[q+2].y * t2.y + a0[q+2].z * t2.z + a0[q+2].w * t2.w;
            d03 += a0[q+3].x * t3.x + a0[q+3].y * t3.y + a0[q+3].z * t3.z + a0[q+3].w * t3.w;
            d10 += a1[q].x * t0.x + a1[q].y * t0.y + a1[q].z * t0.z + a1[q].w * t0.w;
            d11 += a1[q+1].x * t1.x + a1[q+1].y * t1.y + a1[q+1].z * t1.z + a1[q+1].w * t1.w;
            d12 += a1[q+2].x * t2.x + a1[q+2].y * t2.y + a1[q+2].z * t2.z + a1[q+2].w * t2.w;
            d13 += a1[q+3].x * t3.x + a1[q+3].y * t3.y + a1[q+3].z * t3.z + a1[q+3].w * t3.w;
        }
        s0 += __expf(fmaf(d00 + d01 + d02 + d03, 5.0f, -5.0f));
        s1 += __expf(fmaf(d10 + d11 + d12 + d13, 5.0f, -5.0f));
    }
    size_t base = (size_t)blockIdx.z * BSZ;
    g_part[(base + i0) * SSL_NSPLIT + blockIdx.y] = s0;
    g_part[(base + i0 + 128) * SSL_NSPLIT + blockIdx.y] = s1;
}

// ---- SSL combine: ttl = 5 + log(sum partials); subtract pos score ----
__global__ void k_sslfin(const float* __restrict__ v1u, const float* __restrict__ v2u,
                         const float* __restrict__ v1i, const float* __restrict__ v2i) {
    __shared__ float sh[8];
    const float* v1 = blockIdx.y ? v1i : v1u;
    const float* v2 = blockIdx.y ? v2i : v2u;
    int i = blockIdx.x * blockDim.x + threadIdx.x;
    float s = 0.f;
    size_t base = ((size_t)blockIdx.y * BSZ + i) * SSL_NSPLIT;
#pragma unroll
    for (int c = 0; c < SSL_NSPLIT; c++) s += g_part[base + c];
    float ttl = 5.0f + logf(s);
    const float4* af = (const float4*)v1 + (size_t)i * 16;
    const float4* bf = (const float4*)v2 + (size_t)i * 16;
    float pd = 0.f;
#pragma unroll
    for (int q = 0; q < 16; q++) {
        float4 x = af[q], y = bf[q];
        pd += x.x * y.x + x.y * y.y + x.z * y.z + x.w * y.w;
    }
    float val = ttl - pd * 5.0f;
    val = wred(val);
    int lane = threadIdx.x & 31, w = threadIdx.x >> 5;
    if (lane == 0) sh[w] = val;
    __syncthreads();
    if (threadIdx.x == 0) {
        float a = 0.f;
#pragma unroll
        for (int q = 0; q < 8; q++) a += sh[q];
        atomicAdd(&g_acc[2 + blockIdx.y], a);
    }
}

__global__ void k_final(float* __restrict__ out) {
    if (threadIdx.x == 0) {
        out[0] = g_acc[0] / (float)BSZ;
        out[1] = REG_LAMBDA * 0.5f * g_acc[1] / (float)BSZ;
        out[2] = SSL_LAMBDA * (g_acc[2] / (float)BSZ + g_acc[3] / (float)BSZ);
    }
}

extern "C" void kernel_launch(void* const* d_in, const int* in_sizes, int n_in,
                              void* d_out, int out_size) {
    const float* ut   = (const float*)d_in[0];
    const float* itab = (const float*)d_in[1];
    const float* eval = (const float*)d_in[2];
    const float* noise= (const float*)d_in[3];
    const int*   esrc = (const int*)d_in[4];
    const int*   edst = (const int*)d_in[5];
    const int*   user = (const int*)d_in[6];
    const int*   pos  = (const int*)d_in[7];
    const int*   neg  = (const int*)d_in[8];
    float* out = (float*)d_out;

    __half2 *pxh, *pyh;
    float *pcl, *pucl, *puemb, *picl, *piemb;
    cudaGetSymbolAddress((void**)&pxh, g_xh);
    cudaGetSymbolAddress((void**)&pyh, g_yh);
    cudaGetSymbolAddress((void**)&pcl, g_cl);
    cudaGetSymbolAddress((void**)&pucl, g_vucl);
    cudaGetSymbolAddress((void**)&puemb, g_vuemb);
    cudaGetSymbolAddress((void**)&picl, g_vicl);
    cudaGetSymbolAddress((void**)&piemb, g_viemb);

    const int eb = (E2 + 255) / 256;
    const int lb = (N_CNT * 32 + 255) / 256;

    k_init<<<(N_CNT * 32 + 255) / 256, 256>>>(ut, itab);
    k_hist<<<eb, 256>>>(esrc);
    k_scan1<<<SCAN_BLOCKS, 1024>>>();
    k_scan2<<<1, 32>>>();
    k_scan3<<<(N_CNT + 256) / 256, 256>>>();
    k_scatter<<<eb, 256>>>(esrc, edst, eval);

    k_layer<<<lb, 256>>>(pxh, pyh, noise, pcl, 1);
    k_layer<<<lb, 256>>>(pyh, pxh, noise + (size_t)ND, nullptr, 0);
    k_layer<<<lb, 256>>>(pxh, pyh, noise + 2 * (size_t)ND, nullptr, 0);

    k_prep<<<(BSZ * 32 + 255) / 256, 256>>>(user, pos);
    k_bpr<<<(BSZ * 32 + 255) / 256, 256>>>(ut, itab, user, pos, neg);

    dim3 sg(BSZ / 256, SSL_NSPLIT, 2);
    k_ssl2<<<sg, 128>>>(pucl, puemb, picl, piemb);
    dim3 fg(BSZ / 256, 2);
    k_sslfin<<<fg, 256>>>(pucl, puemb, picl, piemb);

    k_final<<<1, 32>>>(out);
}

// round 4
// speedup vs baseline: 2.6630x; 1.5055x over previous
#include <cuda_runtime.h>
#include <cuda_fp16.h>
#include <math.h>

#define U_CNT 50000
#define I_CNT 25000
#define DIM 64
#define N_CNT 75000
#define E2 2000000
#define BSZ 4096
#define ND (N_CNT*DIM)
#define EPSV 0.2f
#define REG_LAMBDA 1e-4f
#define SSL_LAMBDA 0.2f
#define SCAN_BLOCKS 74   // ceil(75001/1024)
#define SSL_NSPLIT 32
#define BLDK 72          // padded smem row (halves): 144B = 9*16B, conflict-free

// ---- device scratch (static allocation only) ----
__device__ __align__(256) __half2 g_xh[N_CNT * 32];   // fp16 ping
__device__ __align__(256) __half2 g_yh[N_CNT * 32];   // fp16 pong
__device__ __align__(256) float g_sum[ND];            // fp32 accumulation
__device__ __align__(256) float g_cl[ND];             // fp32 CL snapshot
__device__ __align__(16) int2  g_epack[E2];
__device__ int g_off[N_CNT + 8];
__device__ int g_scan[N_CNT + 8];
__device__ int g_wp[N_CNT + 8];
__device__ int g_bsum[SCAN_BLOCKS];
__device__ int g_boff[SCAN_BLOCKS];
__device__ __align__(16) float g_vucl[BSZ*DIM];
__device__ __align__(16) float g_vuemb[BSZ*DIM];
__device__ __align__(16) float g_vicl[BSZ*DIM];
__device__ __align__(16) float g_viemb[BSZ*DIM];
__device__ __align__(16) __half2 g_h1[2 * BSZ * 32];  // fp16 normalized cl  (user, item)
__device__ __align__(16) __half2 g_h2[2 * BSZ * 32];  // fp16 normalized emb (user, item)
__device__ float g_part[2 * BSZ * SSL_NSPLIT];
__device__ float g_acc[4];   // 0: bpr, 1: reg, 2: ssl_user, 3: ssl_item

__device__ __forceinline__ float wred(float v) {
#pragma unroll
    for (int o = 16; o; o >>= 1) v += __shfl_xor_sync(0xffffffffu, v, o);
    return v;
}
__device__ __forceinline__ int wscan_i(int v, int lane) {
#pragma unroll
    for (int o = 1; o < 32; o <<= 1) {
        int t = __shfl_up_sync(0xffffffffu, v, o);
        if (lane >= o) v += t;
    }
    return v;
}

// ---- init: xh = fp16(concat(tables)); zero histogram + acc ----
__global__ void k_init(const float* __restrict__ ut, const float* __restrict__ itab) {
    int i = blockIdx.x * blockDim.x + threadIdx.x;   // half2 index
    if (i < N_CNT * 32) {
        int fi = i * 2;
        float a = (fi < U_CNT * DIM) ? ut[fi] : itab[fi - U_CNT * DIM];
        float b = (fi + 1 < U_CNT * DIM) ? ut[fi + 1] : itab[fi + 1 - U_CNT * DIM];
        g_xh[i] = __floats2half2_rn(a, b);
    }
    if (i <= N_CNT) g_off[i] = 0;
    if (i < 4) g_acc[i] = 0.f;
}

__global__ void k_hist(const int* __restrict__ src) {
    int e = blockIdx.x * blockDim.x + threadIdx.x;
    if (e < E2) atomicAdd(&g_off[src[e] + 1], 1);
}

__global__ void k_scan1() {
    __shared__ int ws[32];
    int i = blockIdx.x * 1024 + threadIdx.x;
    int v = (i <= N_CNT) ? g_off[i] : 0;
    int lane = threadIdx.x & 31, wid = threadIdx.x >> 5;
    int s = wscan_i(v, lane);
    if (lane == 31) ws[wid] = s;
    __syncthreads();
    if (wid == 0) { int t = ws[lane]; t = wscan_i(t, lane); ws[lane] = t; }
    __syncthreads();
    if (wid) s += ws[wid - 1];
    if (i <= N_CNT) g_scan[i] = s;
    if (threadIdx.x == 1023) g_bsum[blockIdx.x] = s;
}

__global__ void k_scan2() {
    int lane = threadIdx.x;
    int v0 = (lane < SCAN_BLOCKS) ? g_bsum[lane] : 0;
    int v1 = (32 + lane < SCAN_BLOCKS) ? g_bsum[32 + lane] : 0;
    int v2 = (64 + lane < SCAN_BLOCKS) ? g_bsum[64 + lane] : 0;
    int s0 = wscan_i(v0, lane);
    int t0 = __shfl_sync(0xffffffffu, s0, 31);
    int s1 = wscan_i(v1, lane) + t0;
    int t1 = __shfl_sync(0xffffffffu, s1, 31);
    int s2 = wscan_i(v2, lane) + t1;
    if (lane < SCAN_BLOCKS) g_boff[lane] = s0 - v0;
    if (32 + lane < SCAN_BLOCKS) g_boff[32 + lane] = s1 - v1;
    if (64 + lane < SCAN_BLOCKS) g_boff[64 + lane] = s2 - v2;
}

__global__ void k_scan3() {
    int i = blockIdx.x * blockDim.x + threadIdx.x;
    if (i <= N_CNT) {
        int v = g_scan[i] + g_boff[i >> 10];
        g_off[i] = v;
        if (i < N_CNT) g_wp[i] = v;
    }
}

__global__ void k_scatter(const int* __restrict__ src, const int* __restrict__ dst,
                          const float* __restrict__ val) {
    int e = blockIdx.x * blockDim.x + threadIdx.x;
    if (e >= E2) return;
    int r = src[e];
    int p = atomicAdd(&g_wp[r], 1);
    g_epack[p] = make_int2(dst[e], __float_as_int(val[e]));
}

// ---- fused layer: fp16 CSR gather (fp32 accum) + perturb + mean-accum + CL snapshot ----
__global__ void k_layer(const __half2* __restrict__ xin, __half2* __restrict__ xout,
                        const float* __restrict__ noise, float* __restrict__ cl, int first) {
    int gt = blockIdx.x * blockDim.x + threadIdx.x;
    int row = gt >> 5, lane = gt & 31;
    if (row >= N_CNT) return;
    int k = g_off[row], end = g_off[row + 1];
    float ax = 0.f, ay = 0.f;
    int n4 = k + ((end - k) & ~3);
    for (; k < n4; k += 4) {
        int2 e0 = __ldg(&g_epack[k]);
        int2 e1 = __ldg(&g_epack[k + 1]);
        int2 e2 = __ldg(&g_epack[k + 2]);
        int2 e3 = __ldg(&g_epack[k + 3]);
        float2 v0 = __half22float2(__ldg(xin + (size_t)e0.x * 32 + lane));
        float2 v1 = __half22float2(__ldg(xin + (size_t)e1.x * 32 + lane));
        float2 v2 = __half22float2(__ldg(xin + (size_t)e2.x * 32 + lane));
        float2 v3 = __half22float2(__ldg(xin + (size_t)e3.x * 32 + lane));
        float w0 = __int_as_float(e0.y), w1 = __int_as_float(e1.y);
        float w2 = __int_as_float(e2.y), w3 = __int_as_float(e3.y);
        ax = fmaf(w0, v0.x, fmaf(w1, v1.x, fmaf(w2, v2.x, fmaf(w3, v3.x, ax))));
        ay = fmaf(w0, v0.y, fmaf(w1, v1.y, fmaf(w2, v2.y, fmaf(w3, v3.y, ay))));
    }
    for (; k < end; k++) {
        int2 e0 = __ldg(&g_epack[k]);
        float2 v0 = __half22float2(__ldg(xin + (size_t)e0.x * 32 + lane));
        float w0 = __int_as_float(e0.y);
        ax = fmaf(w0, v0.x, ax);
        ay = fmaf(w0, v0.y, ay);
    }
    size_t off = (size_t)row * DIM + lane * 2;
    float2 nz = *(const float2*)(noise + off);
    float ss = wred(nz.x * nz.x + nz.y * nz.y);
    float sc = EPSV / fmaxf(sqrtf(ss), 1e-12f);
    float sx = (ax > 0.f) ? 1.f : ((ax < 0.f) ? -1.f : 0.f);
    float sy = (ay > 0.f) ? 1.f : ((ay < 0.f) ? -1.f : 0.f);
    ax += sx * nz.x * sc;
    ay += sy * nz.y * sc;
    xout[(size_t)row * 32 + lane] = __floats2half2_rn(ax, ay);
    float2 sm;
    if (first) sm = make_float2(ax, ay);
    else { sm = *(float2*)(g_sum + off); sm.x += ax; sm.y += ay; }
    *(float2*)(g_sum + off) = sm;
    if (cl) *(float2*)(cl + off) = make_float2(ax, ay);
}

// ---- normalize + write fp32 copy and fp16 copy ----
__device__ __forceinline__ void norm_copy(const float* __restrict__ srcrow,
                                          float* __restrict__ dstrow,
                                          __half2* __restrict__ hdst, int lane) {
    float2 v = *(const float2*)(srcrow + lane * 2);
    float ss = wred(v.x * v.x + v.y * v.y);
    float inv = 1.f / fmaxf(sqrtf(ss), 1e-12f);
    float2 o = make_float2(v.x * inv, v.y * inv);
    *(float2*)(dstrow + lane * 2) = o;
    hdst[lane] = __floats2half2_rn(o.x, o.y);
}

// ---- merged prep (blocks [0,512)) + bpr (blocks [512,1024)) ----
__global__ void k_prepbpr(const int* __restrict__ user, const int* __restrict__ pos,
                          const int* __restrict__ neg,
                          const float* __restrict__ ut, const float* __restrict__ itab) {
    if (blockIdx.x < 512) {
        int gt = blockIdx.x * blockDim.x + threadIdx.x;
        int k = gt >> 5, lane = gt & 31;
        size_t ru = (size_t)user[k] * DIM;
        size_t ri = (size_t)(U_CNT + pos[k]) * DIM;
        norm_copy(g_cl + ru,  g_vucl  + (size_t)k * DIM, g_h1 + (size_t)k * 32, lane);
        norm_copy(g_sum + ru, g_vuemb + (size_t)k * DIM, g_h2 + (size_t)k * 32, lane);
        norm_copy(g_cl + ri,  g_vicl  + (size_t)k * DIM, g_h1 + (size_t)(BSZ + k) * 32, lane);
        norm_copy(g_sum + ri, g_viemb + (size_t)k * DIM, g_h2 + (size_t)(BSZ + k) * 32, lane);
        return;
    }
    __shared__ float sh0[8], sh1[8];
    int gt = (blockIdx.x - 512) * blockDim.x + threadIdx.x;
    int k = gt >> 5, lane = gt & 31, w = threadIdx.x >> 5;
    float sp = 0.f, rg = 0.f;
    {
        int iu = user[k], ip = pos[k], ineg = neg[k];
        const float c = 1.f / 3.f;
        float2 ue = *(const float2*)(g_sum + (size_t)iu * DIM + lane * 2);
        float2 pe = *(const float2*)(g_sum + (size_t)(U_CNT + ip) * DIM + lane * 2);
        float2 ne = *(const float2*)(g_sum + (size_t)(U_CNT + ineg) * DIM + lane * 2);
        ue.x *= c; ue.y *= c; pe.x *= c; pe.y *= c; ne.x *= c; ne.y *= c;
        float ps = wred(ue.x * pe.x + ue.y * pe.y);
        float ns = wred(ue.x * ne.x + ue.y * ne.y);
        float2 a = *(const float2*)(ut + (size_t)iu * DIM + lane * 2);
        float2 b = *(const float2*)(itab + (size_t)ip * DIM + lane * 2);
        float2 d = *(const float2*)(itab + (size_t)ineg * DIM + lane * 2);
        float r = wred(a.x * a.x + a.y * a.y + b.x * b.x + b.y * b.y + d.x * d.x + d.y * d.y);
        if (lane == 0) {
            float z = ns - ps;
            sp = fmaxf(z, 0.f) + log1pf(expf(-fabsf(z)));
            rg = r;
        }
    }
    if (lane == 0) { sh0[w] = sp; sh1[w] = rg; }
    __syncthreads();
    if (threadIdx.x == 0) {
        float a = 0.f, b = 0.f;
#pragma unroll
        for (int i = 0; i < 8; i++) { a += sh0[i]; b += sh1[i]; }
        atomicAdd(&g_acc[0], a);
        atomicAdd(&g_acc[1], b);
    }
}

// ---- SSL via HMMA: per block 128x128 tile of S = v1 @ v2^T; exp+rowsum epilogue in regs.
//      |dot|<=1 (normalized) -> fixed-shift logsumexp with max = 1/TEMP = 5. ----
__global__ void __launch_bounds__(256) k_sslmma() {
    __shared__ __align__(16) __half bt[128 * BLDK];
    const __half* h1 = (const __half*)(g_h1 + (size_t)blockIdx.z * BSZ * 32);
    const __half* h2 = (const __half*)(g_h2 + (size_t)blockIdx.z * BSZ * 32);
    int tid = threadIdx.x, warp = tid >> 5, lane = tid & 31;
    int r = lane >> 2, c = lane & 3;
    // cooperative B tile load: rows j0..j0+127 of v2 (n-major [n][k])
    int j0 = blockIdx.y * 128;
    {
        int row = tid >> 1, off = (tid & 1) * 32;
        const uint4* src = (const uint4*)(h2 + (size_t)(j0 + row) * 64 + off);
        uint4* dst = (uint4*)(bt + row * BLDK + off);
#pragma unroll
        for (int i = 0; i < 4; i++) dst[i] = src[i];
    }
    // A fragments: this warp's 16 rows, full k=64 (4 chunks x 4 b32)
    int i0 = blockIdx.x * 128 + warp * 16;
    unsigned a[16];
    {
        const __half* A0 = h1 + (size_t)(i0 + r) * 64;
        const __half* A8 = h1 + (size_t)(i0 + r + 8) * 64;
#pragma unroll
        for (int kc = 0; kc < 4; kc++) {
            int k0 = kc * 16 + 2 * c;
            a[kc * 4 + 0] = *(const unsigned*)(A0 + k0);
            a[kc * 4 + 1] = *(const unsigned*)(A8 + k0);
            a[kc * 4 + 2] = *(const unsigned*)(A0 + k0 + 8);
            a[kc * 4 + 3] = *(const unsigned*)(A8 + k0 + 8);
        }
    }
    __syncthreads();
    float s_lo = 0.f, s_hi = 0.f;
#pragma unroll
    for (int nt = 0; nt < 16; nt++) {
        const __half* Bp = bt + (nt * 8 + r) * BLDK;   // B frag: n = nt*8 + lane/4
        float c0 = 0.f, c1 = 0.f, c2 = 0.f, c3 = 0.f;
#pragma unroll
        for (int kc = 0; kc < 4; kc++) {
            unsigned b0 = *(const unsigned*)(Bp + kc * 16 + 2 * c);
            unsigned b1 = *(const unsigned*)(Bp + kc * 16 + 2 * c + 8);
            asm volatile(
                "mma.sync.aligned.m16n8k16.row.col.f32.f16.f16.f32 "
                "{%0,%1,%2,%3}, {%4,%5,%6,%7}, {%8,%9}, {%0,%1,%2,%3};"
                : "+f"(c0), "+f"(c1), "+f"(c2), "+f"(c3)
                : "r"(a[kc * 4 + 0]), "r"(a[kc * 4 + 1]),
                  "r"(a[kc * 4 + 2]), "r"(a[kc * 4 + 3]),
                  "r"(b0), "r"(b1));
        }
        s_lo += __expf(fmaf(c0, 5.f, -5.f)) + __expf(fmaf(c1, 5.f, -5.f));
        s_hi += __expf(fmaf(c2, 5.f, -5.f)) + __expf(fmaf(c3, 5.f, -5.f));
    }
    s_lo += __shfl_xor_sync(0xffffffffu, s_lo, 1);
    s_lo += __shfl_xor_sync(0xffffffffu, s_lo, 2);
    s_hi += __shfl_xor_sync(0xffffffffu, s_hi, 1);
    s_hi += __shfl_xor_sync(0xffffffffu, s_hi, 2);
    if (c == 0) {
        size_t base = (size_t)blockIdx.z * BSZ;
        g_part[(base + i0 + r) * SSL_NSPLIT + blockIdx.y] = s_lo;
        g_part[(base + i0 + r + 8) * SSL_NSPLIT + blockIdx.y] = s_hi;
    }
}

// ---- SSL combine: ttl = 5 + log(sum partials); subtract pos score (fp32 copies) ----
__global__ void k_sslfin(const float* __restrict__ v1u, const float* __restrict__ v2u,
                         const float* __restrict__ v1i, const float* __restrict__ v2i) {
    __shared__ float sh[8];
    const float* v1 = blockIdx.y ? v1i : v1u;
    const float* v2 = blockIdx.y ? v2i : v2u;
    int i = blockIdx.x * blockDim.x + threadIdx.x;
    float s = 0.f;
    size_t base = ((size_t)blockIdx.y * BSZ + i) * SSL_NSPLIT;
#pragma unroll
    for (int cc = 0; cc < SSL_NSPLIT; cc++) s += g_part[base + cc];
    float ttl = 5.0f + logf(s);
    const float4* af = (const float4*)v1 + (size_t)i * 16;
    const float4* bf = (const float4*)v2 + (size_t)i * 16;
    float pd = 0.f;
#pragma unroll
    for (int q = 0; q < 16; q++) {
        float4 x = af[q], y = bf[q];
        pd += x.x * y.x + x.y * y.y + x.z * y.z + x.w * y.w;
    }
    float val = ttl - pd * 5.0f;
    val = wred(val);
    int lane = threadIdx.x & 31, w = threadIdx.x >> 5;
    if (lane == 0) sh[w] = val;
    __syncthreads();
    if (threadIdx.x == 0) {
        float a = 0.f;
#pragma unroll
        for (int q = 0; q < 8; q++) a += sh[q];
        atomicAdd(&g_acc[2 + blockIdx.y], a);
    }
}

__global__ void k_final(float* __restrict__ out) {
    if (threadIdx.x == 0) {
        out[0] = g_acc[0] / (float)BSZ;
        out[1] = REG_LAMBDA * 0.5f * g_acc[1] / (float)BSZ;
        out[2] = SSL_LAMBDA * (g_acc[2] / (float)BSZ + g_acc[3] / (float)BSZ);
    }
}

extern "C" void kernel_launch(void* const* d_in, const int* in_sizes, int n_in,
                              void* d_out, int out_size) {
    const float* ut   = (const float*)d_in[0];
    const float* itab = (const float*)d_in[1];
    const float* eval = (const float*)d_in[2];
    const float* noise= (const float*)d_in[3];
    const int*   esrc = (const int*)d_in[4];
    const int*   edst = (const int*)d_in[5];
    const int*   user = (const int*)d_in[6];
    const int*   pos  = (const int*)d_in[7];
    const int*   neg  = (const int*)d_in[8];
    float* out = (float*)d_out;

    __half2 *pxh, *pyh;
    float *pcl, *pucl, *puemb, *picl, *piemb;
    cudaGetSymbolAddress((void**)&pxh, g_xh);
    cudaGetSymbolAddress((void**)&pyh, g_yh);
    cudaGetSymbolAddress((void**)&pcl, g_cl);
    cudaGetSymbolAddress((void**)&pucl, g_vucl);
    cudaGetSymbolAddress((void**)&puemb, g_vuemb);
    cudaGetSymbolAddress((void**)&picl, g_vicl);
    cudaGetSymbolAddress((void**)&piemb, g_viemb);

    const int eb = (E2 + 255) / 256;
    const int lb = (N_CNT * 32 + 255) / 256;

    k_init<<<(N_CNT * 32 + 255) / 256, 256>>>(ut, itab);
    k_hist<<<eb, 256>>>(esrc);
    k_scan1<<<SCAN_BLOCKS, 1024>>>();
    k_scan2<<<1, 32>>>();
    k_scan3<<<(N_CNT + 256) / 256, 256>>>();
    k_scatter<<<eb, 256>>>(esrc, edst, eval);

    k_layer<<<lb, 256>>>(pxh, pyh, noise, pcl, 1);
    k_layer<<<lb, 256>>>(pyh, pxh, noise + (size_t)ND, nullptr, 0);
    k_layer<<<lb, 256>>>(pxh, pyh, noise + 2 * (size_t)ND, nullptr, 0);

    k_prepbpr<<<1024, 256>>>(user, pos, neg, ut, itab);

    dim3 sg(BSZ / 128, BSZ / 128, 2);
    k_sslmma<<<sg, 256>>>();
    dim3 fg(BSZ / 256, 2);
    k_sslfin<<<fg, 256>>>(pucl, puemb, picl, piemb);

    k_final<<<1, 32>>>(out);
}

// round 5
// speedup vs baseline: 2.6634x; 1.0001x over previous
#include <cuda_runtime.h>
#include <cuda_fp16.h>
#include <cuda_fp8.h>
#include <math.h>

#define U_CNT 50000
#define I_CNT 25000
#define DIM 64
#define N_CNT 75000
#define E2 2000000
#define BSZ 4096
#define ND (N_CNT*DIM)
#define EPSV 0.2f
#define REG_LAMBDA 1e-4f
#define SSL_LAMBDA 0.2f
#define SCAN_BLOCKS 74   // ceil(75001/1024)
#define SSL_NSPLIT 32
#define BLDK 72          // padded smem row (halves): 144B = 9*16B, conflict-free
#define FSCALE 64.0f
#define INV_FSCALE 0.015625f

// ---- device scratch (static allocation only) ----
__device__ __align__(256) unsigned short g_x8[N_CNT * 32];   // fp8x2 ping (x * 64)
__device__ __align__(256) unsigned short g_y8[N_CNT * 32];   // fp8x2 pong
__device__ __align__(256) float g_sum[ND];            // fp32 accumulation
__device__ __align__(256) float g_cl[ND];             // fp32 CL snapshot
__device__ __align__(16) int2  g_epack[E2];
__device__ int g_off[N_CNT + 8];
__device__ int g_scan[N_CNT + 8];
__device__ int g_wp[N_CNT + 8];
__device__ int g_bsum[SCAN_BLOCKS];
__device__ int g_boff[SCAN_BLOCKS];
__device__ int g_ctr1, g_ctr2;
__device__ __align__(16) float g_vucl[BSZ*DIM];
__device__ __align__(16) float g_vuemb[BSZ*DIM];
__device__ __align__(16) float g_vicl[BSZ*DIM];
__device__ __align__(16) float g_viemb[BSZ*DIM];
__device__ __align__(16) __half2 g_h1[2 * BSZ * 32];  // fp16 normalized cl  (user, item)
__device__ __align__(16) __half2 g_h2[2 * BSZ * 32];  // fp16 normalized emb (user, item)
__device__ float g_part[2 * BSZ * SSL_NSPLIT];
__device__ float g_acc[4];   // 0: bpr, 1: reg, 2: ssl_user, 3: ssl_item

__device__ __forceinline__ float wred(float v) {
#pragma unroll
    for (int o = 16; o; o >>= 1) v += __shfl_xor_sync(0xffffffffu, v, o);
    return v;
}
__device__ __forceinline__ int wscan_i(int v, int lane) {
#pragma unroll
    for (int o = 1; o < 32; o <<= 1) {
        int t = __shfl_up_sync(0xffffffffu, v, o);
        if (lane >= o) v += t;
    }
    return v;
}
__device__ __forceinline__ float2 fp8x2_to_f2(unsigned short u) {
    __half2_raw hr = __nv_cvt_fp8x2_to_halfraw2((__nv_fp8x2_storage_t)u, __NV_E4M3);
    return __half22float2(*(__half2*)&hr);
}
__device__ __forceinline__ unsigned short f2_to_fp8x2(float a, float b) {
    return (unsigned short)__nv_cvt_float2_to_fp8x2(make_float2(a, b), __NV_SATFINITE, __NV_E4M3);
}

// ---- init: x8 = fp8(64 * concat(tables)); zero histogram + acc + counters ----
__global__ void k_init(const float* __restrict__ ut, const float* __restrict__ itab) {
    int i = blockIdx.x * blockDim.x + threadIdx.x;   // fp8x2 index
    if (i < N_CNT * 32) {
        int fi = i * 2;
        float a = (fi < U_CNT * DIM) ? ut[fi] : itab[fi - U_CNT * DIM];
        float b = (fi + 1 < U_CNT * DIM) ? ut[fi + 1] : itab[fi + 1 - U_CNT * DIM];
        g_x8[i] = f2_to_fp8x2(a * FSCALE, b * FSCALE);
    }
    if (i <= N_CNT) g_off[i] = 0;
    if (i < 4) g_acc[i] = 0.f;
    if (i == 0) { g_ctr1 = 0; g_ctr2 = 0; }
}

__global__ void k_hist(const int* __restrict__ src) {
    int e = blockIdx.x * blockDim.x + threadIdx.x;
    if (e < E2) atomicAdd(&g_off[src[e] + 1], 1);
}

// ---- block scan of g_off; last block also scans the block totals (fused scan1+scan2) ----
__global__ void k_scan12() {
    __shared__ int ws[32];
    __shared__ int lastf;
    int i = blockIdx.x * 1024 + threadIdx.x;
    int v = (i <= N_CNT) ? g_off[i] : 0;
    int lane = threadIdx.x & 31, wid = threadIdx.x >> 5;
    int s = wscan_i(v, lane);
    if (lane == 31) ws[wid] = s;
    __syncthreads();
    if (wid == 0) { int t = ws[lane]; t = wscan_i(t, lane); ws[lane] = t; }
    __syncthreads();
    if (wid) s += ws[wid - 1];
    if (i <= N_CNT) g_scan[i] = s;
    if (threadIdx.x == 1023) g_bsum[blockIdx.x] = s;
    __threadfence();
    __syncthreads();
    if (threadIdx.x == 0) lastf = (atomicAdd(&g_ctr1, 1) == SCAN_BLOCKS - 1);
    __syncthreads();
    if (lastf && threadIdx.x < 32) {
        int v0 = (lane < SCAN_BLOCKS) ? g_bsum[lane] : 0;
        int v1 = (32 + lane < SCAN_BLOCKS) ? g_bsum[32 + lane] : 0;
        int v2 = (64 + lane < SCAN_BLOCKS) ? g_bsum[64 + lane] : 0;
        int s0 = wscan_i(v0, lane);
        int t0 = __shfl_sync(0xffffffffu, s0, 31);
        int s1 = wscan_i(v1, lane) + t0;
        int t1 = __shfl_sync(0xffffffffu, s1, 31);
        int s2 = wscan_i(v2, lane) + t1;
        if (lane < SCAN_BLOCKS) g_boff[lane] = s0 - v0;
        if (32 + lane < SCAN_BLOCKS) g_boff[32 + lane] = s1 - v1;
        if (64 + lane < SCAN_BLOCKS) g_boff[64 + lane] = s2 - v2;
    }
}

__global__ void k_scan3() {
    int i = blockIdx.x * blockDim.x + threadIdx.x;
    if (i <= N_CNT) {
        int v = g_scan[i] + g_boff[i >> 10];
        g_off[i] = v;
        if (i < N_CNT) g_wp[i] = v;
    }
}

__global__ void k_scatter(const int* __restrict__ src, const int* __restrict__ dst,
                          const float* __restrict__ val) {
    int e = blockIdx.x * blockDim.x + threadIdx.x;
    if (e >= E2) return;
    int r = src[e];
    int p = atomicAdd(&g_wp[r], 1);
    g_epack[p] = make_int2(dst[e], __float_as_int(val[e]));
}

// ---- fused layer: fp8 CSR gather (fp32 accum) + perturb + mean-accum + CL snapshot.
//      Buffer holds x*64 in e4m3; exact fp32 path goes to g_sum/g_cl. ----
__global__ void k_layer(const unsigned short* __restrict__ xin,
                        unsigned short* __restrict__ xout,
                        const float* __restrict__ noise, float* __restrict__ cl, int first) {
    int gt = blockIdx.x * blockDim.x + threadIdx.x;
    int row = gt >> 5, lane = gt & 31;
    if (row >= N_CNT) return;
    int k = g_off[row], end = g_off[row + 1];
    float ax = 0.f, ay = 0.f;
    int n4 = k + ((end - k) & ~3);
    for (; k < n4; k += 4) {
        int2 e0 = __ldg(&g_epack[k]);
        int2 e1 = __ldg(&g_epack[k + 1]);
        int2 e2 = __ldg(&g_epack[k + 2]);
        int2 e3 = __ldg(&g_epack[k + 3]);
        float2 v0 = fp8x2_to_f2(__ldg(xin + (size_t)e0.x * 32 + lane));
        float2 v1 = fp8x2_to_f2(__ldg(xin + (size_t)e1.x * 32 + lane));
        float2 v2 = fp8x2_to_f2(__ldg(xin + (size_t)e2.x * 32 + lane));
        float2 v3 = fp8x2_to_f2(__ldg(xin + (size_t)e3.x * 32 + lane));
        float w0 = __int_as_float(e0.y), w1 = __int_as_float(e1.y);
        float w2 = __int_as_float(e2.y), w3 = __int_as_float(e3.y);
        ax = fmaf(w0, v0.x, fmaf(w1, v1.x, fmaf(w2, v2.x, fmaf(w3, v3.x, ax))));
        ay = fmaf(w0, v0.y, fmaf(w1, v1.y, fmaf(w2, v2.y, fmaf(w3, v3.y, ay))));
    }
    for (; k < end; k++) {
        int2 e0 = __ldg(&g_epack[k]);
        float2 v0 = fp8x2_to_f2(__ldg(xin + (size_t)e0.x * 32 + lane));
        float w0 = __int_as_float(e0.y);
        ax = fmaf(w0, v0.x, ax);
        ay = fmaf(w0, v0.y, ay);
    }
    ax *= INV_FSCALE; ay *= INV_FSCALE;   // undo buffer scale
    size_t off = (size_t)row * DIM + lane * 2;
    float2 nz = *(const float2*)(noise + off);
    float ss = wred(nz.x * nz.x + nz.y * nz.y);
    float sc = EPSV / fmaxf(sqrtf(ss), 1e-12f);
    float sx = (ax > 0.f) ? 1.f : ((ax < 0.f) ? -1.f : 0.f);
    float sy = (ay > 0.f) ? 1.f : ((ay < 0.f) ? -1.f : 0.f);
    ax += sx * nz.x * sc;
    ay += sy * nz.y * sc;
    if (xout) xout[(size_t)row * 32 + lane] = f2_to_fp8x2(ax * FSCALE, ay * FSCALE);
    float2 sm;
    if (first) sm = make_float2(ax, ay);
    else { sm = *(float2*)(g_sum + off); sm.x += ax; sm.y += ay; }
    *(float2*)(g_sum + off) = sm;
    if (cl) *(float2*)(cl + off) = make_float2(ax, ay);
}

// ---- normalize + write fp32 copy and fp16 copy ----
__device__ __forceinline__ void norm_copy(const float* __restrict__ srcrow,
                                          float* __restrict__ dstrow,
                                          __half2* __restrict__ hdst, int lane) {
    float2 v = *(const float2*)(srcrow + lane * 2);
    float ss = wred(v.x * v.x + v.y * v.y);
    float inv = 1.f / fmaxf(sqrtf(ss), 1e-12f);
    float2 o = make_float2(v.x * inv, v.y * inv);
    *(float2*)(dstrow + lane * 2) = o;
    hdst[lane] = __floats2half2_rn(o.x, o.y);
}

// ---- merged prep (blocks [0,512)) + bpr (blocks [512,1024)) ----
__global__ void k_prepbpr(const int* __restrict__ user, const int* __restrict__ pos,
                          const int* __restrict__ neg,
                          const float* __restrict__ ut, const float* __restrict__ itab) {
    if (blockIdx.x < 512) {
        int gt = blockIdx.x * blockDim.x + threadIdx.x;
        int k = gt >> 5, lane = gt & 31;
        size_t ru = (size_t)user[k] * DIM;
        size_t ri = (size_t)(U_CNT + pos[k]) * DIM;
        norm_copy(g_cl + ru,  g_vucl  + (size_t)k * DIM, g_h1 + (size_t)k * 32, lane);
        norm_copy(g_sum + ru, g_vuemb + (size_t)k * DIM, g_h2 + (size_t)k * 32, lane);
        norm_copy(g_cl + ri,  g_vicl  + (size_t)k * DIM, g_h1 + (size_t)(BSZ + k) * 32, lane);
        norm_copy(g_sum + ri, g_viemb + (size_t)k * DIM, g_h2 + (size_t)(BSZ + k) * 32, lane);
        return;
    }
    __shared__ float sh0[8], sh1[8];
    int gt = (blockIdx.x - 512) * blockDim.x + threadIdx.x;
    int k = gt >> 5, lane = gt & 31, w = threadIdx.x >> 5;
    float sp = 0.f, rg = 0.f;
    {
        int iu = user[k], ip = pos[k], ineg = neg[k];
        const float c = 1.f / 3.f;
        float2 ue = *(const float2*)(g_sum + (size_t)iu * DIM + lane * 2);
        float2 pe = *(const float2*)(g_sum + (size_t)(U_CNT + ip) * DIM + lane * 2);
        float2 ne = *(const float2*)(g_sum + (size_t)(U_CNT + ineg) * DIM + lane * 2);
        ue.x *= c; ue.y *= c; pe.x *= c; pe.y *= c; ne.x *= c; ne.y *= c;
        float ps = wred(ue.x * pe.x + ue.y * pe.y);
        float ns = wred(ue.x * ne.x + ue.y * ne.y);
        float2 a = *(const float2*)(ut + (size_t)iu * DIM + lane * 2);
        float2 b = *(const float2*)(itab + (size_t)ip * DIM + lane * 2);
        float2 d = *(const float2*)(itab + (size_t)ineg * DIM + lane * 2);
        float r = wred(a.x * a.x + a.y * a.y + b.x * b.x + b.y * b.y + d.x * d.x + d.y * d.y);
        if (lane == 0) {
            float z = ns - ps;
            sp = fmaxf(z, 0.f) + log1pf(expf(-fabsf(z)));
            rg = r;
        }
    }
    if (lane == 0) { sh0[w] = sp; sh1[w] = rg; }
    __syncthreads();
    if (threadIdx.x == 0) {
        float a = 0.f, b = 0.f;
#pragma unroll
        for (int i = 0; i < 8; i++) { a += sh0[i]; b += sh1[i]; }
        atomicAdd(&g_acc[0], a);
        atomicAdd(&g_acc[1], b);
    }
}

// ---- SSL via HMMA: per block 128x128 tile of S = v1 @ v2^T; exp+rowsum epilogue in regs ----
__global__ void __launch_bounds__(256) k_sslmma() {
    __shared__ __align__(16) __half bt[128 * BLDK];
    const __half* h1 = (const __half*)(g_h1 + (size_t)blockIdx.z * BSZ * 32);
    const __half* h2 = (const __half*)(g_h2 + (size_t)blockIdx.z * BSZ * 32);
    int tid = threadIdx.x, warp = tid >> 5, lane = tid & 31;
    int r = lane >> 2, c = lane & 3;
    int j0 = blockIdx.y * 128;
    {
        int row = tid >> 1, off = (tid & 1) * 32;
        const uint4* src = (const uint4*)(h2 + (size_t)(j0 + row) * 64 + off);
        uint4* dst = (uint4*)(bt + row * BLDK + off);
#pragma unroll
        for (int i = 0; i < 4; i++) dst[i] = src[i];
    }
    int i0 = blockIdx.x * 128 + warp * 16;
    unsigned a[16];
    {
        const __half* A0 = h1 + (size_t)(i0 + r) * 64;
        const __half* A8 = h1 + (size_t)(i0 + r + 8) * 64;
#pragma unroll
        for (int kc = 0; kc < 4; kc++) {
            int k0 = kc * 16 + 2 * c;
            a[kc * 4 + 0] = *(const unsigned*)(A0 + k0);
            a[kc * 4 + 1] = *(const unsigned*)(A8 + k0);
            a[kc * 4 + 2] = *(const unsigned*)(A0 + k0 + 8);
            a[kc * 4 + 3] = *(const unsigned*)(A8 + k0 + 8);
        }
    }
    __syncthreads();
    float s_lo = 0.f, s_hi = 0.f;
#pragma unroll
    for (int nt = 0; nt < 16; nt++) {
        const __half* Bp = bt + (nt * 8 + r) * BLDK;
        float c0 = 0.f, c1 = 0.f, c2 = 0.f, c3 = 0.f;
#pragma unroll
        for (int kc = 0; kc < 4; kc++) {
            unsigned b0 = *(const unsigned*)(Bp + kc * 16 + 2 * c);
            unsigned b1 = *(const unsigned*)(Bp + kc * 16 + 2 * c + 8);
            asm volatile(
                "mma.sync.aligned.m16n8k16.row.col.f32.f16.f16.f32 "
                "{%0,%1,%2,%3}, {%4,%5,%6,%7}, {%8,%9}, {%0,%1,%2,%3};"
                : "+f"(c0), "+f"(c1), "+f"(c2), "+f"(c3)
                : "r"(a[kc * 4 + 0]), "r"(a[kc * 4 + 1]),
                  "r"(a[kc * 4 + 2]), "r"(a[kc * 4 + 3]),
                  "r"(b0), "r"(b1));
        }
        s_lo += __expf(fmaf(c0, 5.f, -5.f)) + __expf(fmaf(c1, 5.f, -5.f));
        s_hi += __expf(fmaf(c2, 5.f, -5.f)) + __expf(fmaf(c3, 5.f, -5.f));
    }
    s_lo += __shfl_xor_sync(0xffffffffu, s_lo, 1);
    s_lo += __shfl_xor_sync(0xffffffffu, s_lo, 2);
    s_hi += __shfl_xor_sync(0xffffffffu, s_hi, 1);
    s_hi += __shfl_xor_sync(0xffffffffu, s_hi, 2);
    if (c == 0) {
        size_t base = (size_t)blockIdx.z * BSZ;
        g_part[(base + i0 + r) * SSL_NSPLIT + blockIdx.y] = s_lo;
        g_part[(base + i0 + r + 8) * SSL_NSPLIT + blockIdx.y] = s_hi;
    }
}

// ---- SSL combine + final output (last block writes out) ----
__global__ void k_sslfin(const float* __restrict__ v1u, const float* __restrict__ v2u,
                         const float* __restrict__ v1i, const float* __restrict__ v2i,
                         float* __restrict__ out) {
    __shared__ float sh[8];
    const float* v1 = blockIdx.y ? v1i : v1u;
    const float* v2 = blockIdx.y ? v2i : v2u;
    int i = blockIdx.x * blockDim.x + threadIdx.x;
    float s = 0.f;
    size_t base = ((size_t)blockIdx.y * BSZ + i) * SSL_NSPLIT;
#pragma unroll
    for (int cc = 0; cc < SSL_NSPLIT; cc++) s += g_part[base + cc];
    float ttl = 5.0f + logf(s);
    const float4* af = (const float4*)v1 + (size_t)i * 16;
    const float4* bf = (const float4*)v2 + (size_t)i * 16;
    float pd = 0.f;
#pragma unroll
    for (int q = 0; q < 16; q++) {
        float4 x = af[q], y = bf[q];
        pd += x.x * y.x + x.y * y.y + x.z * y.z + x.w * y.w;
    }
    float val = ttl - pd * 5.0f;
    val = wred(val);
    int lane = threadIdx.x & 31, w = threadIdx.x >> 5;
    if (lane == 0) sh[w] = val;
    __syncthreads();
    if (threadIdx.x == 0) {
        float a = 0.f;
#pragma unroll
        for (int q = 0; q < 8; q++) a += sh[q];
        atomicAdd(&g_acc[2 + blockIdx.y], a);
        __threadfence();
        if (atomicAdd(&g_ctr2, 1) == 31) {   // 16 x 2 blocks
            out[0] = g_acc[0] / (float)BSZ;
            out[1] = REG_LAMBDA * 0.5f * g_acc[1] / (float)BSZ;
            out[2] = SSL_LAMBDA * ((g_acc[2] + g_acc[3]) / (float)BSZ);
        }
    }
}

extern "C" void kernel_launch(void* const* d_in, const int* in_sizes, int n_in,
                              void* d_out, int out_size) {
    const float* ut   = (const float*)d_in[0];
    const float* itab = (const float*)d_in[1];
    const float* eval = (const float*)d_in[2];
    const float* noise= (const float*)d_in[3];
    const int*   esrc = (const int*)d_in[4];
    const int*   edst = (const int*)d_in[5];
    const int*   user = (const int*)d_in[6];
    const int*   pos  = (const int*)d_in[7];
    const int*   neg  = (const int*)d_in[8];
    float* out = (float*)d_out;

    unsigned short *px8, *py8;
    float *pcl, *pucl, *puemb, *picl, *piemb;
    cudaGetSymbolAddress((void**)&px8, g_x8);
    cudaGetSymbolAddress((void**)&py8, g_y8);
    cudaGetSymbolAddress((void**)&pcl, g_cl);
    cudaGetSymbolAddress((void**)&pucl, g_vucl);
    cudaGetSymbolAddress((void**)&puemb, g_vuemb);
    cudaGetSymbolAddress((void**)&picl, g_vicl);
    cudaGetSymbolAddress((void**)&piemb, g_viemb);

    const int eb = (E2 + 255) / 256;
    const int lb = (N_CNT * 32 + 255) / 256;

    k_init<<<(N_CNT * 32 + 255) / 256, 256>>>(ut, itab);
    k_hist<<<eb, 256>>>(esrc);
    k_scan12<<<SCAN_BLOCKS, 1024>>>();
    k_scan3<<<(N_CNT + 256) / 256, 256>>>();
    k_scatter<<<eb, 256>>>(esrc, edst, eval);

    k_layer<<<lb, 256>>>(px8, py8, noise, pcl, 1);
    k_layer<<<lb, 256>>>(py8, px8, noise + (size_t)ND, nullptr, 0);
    k_layer<<<lb, 256>>>(px8, nullptr, noise + 2 * (size_t)ND, nullptr, 0);

    k_prepbpr<<<1024, 256>>>(user, pos, neg, ut, itab);

    dim3 sg(BSZ / 128, BSZ / 128, 2);
    k_sslmma<<<sg, 256>>>();
    dim3 fg(BSZ / 256, 2);
    k_sslfin<<<fg, 256>>>(pucl, puemb, picl, piemb, out);
}